// round 12
// baseline (speedup 1.0000x reference)
#include <cuda_runtime.h>
#include <math.h>

// ---------------- problem constants ----------------
#define BB   16     // batch
#define NN   24     // boxes per image
#define CC   149    // 1 obj + 2 xy + 2 wh + 4 head + 120 + 8 + 12
#define NBC  120
#define NEC  8
#define NAC  12
#define IGN_V (-100)
#define IMG  640.0f

#define L_OBJ  1.0f
#define L_BOX  5.0f
#define L_HEAD 2.0f
#define L_ATTR 1.0f

#define T0_CELLS (BB * 80 * 80)   // 102400
#define T1_CELLS (BB * 40 * 40)   // 25600
#define T2_CELLS (BB * 20 * 20)   // 6400
#define TOT_CELLS (T0_CELLS + T1_CELLS + T2_CELLS)  // 134400

#define NWINB  72                  // blocks that ALSO run winner warps (72*16 = 1152)
#define NBLKS  296                 // total blocks = 2 * 148 SMs, one wave
// DRAM-balanced obj slices: winner blocks carry ~12KB of winner gather traffic,
// so they get a smaller obj slice. 72*360 + 224*485 = 134560 >= 134400.
#define WIN_CELLS 360
#define OBJ_CELLS 485
#define OBJ_BASE  (NWINB * WIN_CELLS)   // 25920

// Fixed-point scale for the deterministic integer accumulators.
#define ACC_SCALE 1048576.0        // 2^20

// scratch (device globals). All self-reset -> graph-replay safe.
__device__ unsigned long long g_num  = 0;  // fixed-point loss numerator
__device__ int                g_pos  = 0;  // winner count
__device__ unsigned int       g_done = 0;  // completion counter

__device__ __forceinline__ float ldg_plain(const float* p) {
    float v;
    asm("ld.global.f32 %0, [%1];" : "=f"(v) : "l"(p));
    return v;
}

__device__ __forceinline__ float softplusf(float x) {
    return fmaxf(x, 0.f) + log1pf(expf(-fabsf(x)));
}
__device__ __forceinline__ float sigm(float x) { return 1.f / (1.f + expf(-x)); }
__device__ __forceinline__ float sl1(float p, float t) {
    float d = fabsf(p - t);
    return d < 1.f ? 0.5f * d * d : d - 0.5f;
}
__device__ __forceinline__ float wredf(float v) {
    #pragma unroll
    for (int o = 16; o > 0; o >>= 1) v += __shfl_xor_sync(0xffffffffu, v, o);
    return v;
}
__device__ __forceinline__ float wredmax(float v) {
    #pragma unroll
    for (int o = 16; o > 0; o >>= 1) v = fmaxf(v, __shfl_xor_sync(0xffffffffu, v, o));
    return v;
}

// ---------------------------------------------------------------------------
// Winner role: ONE WARP per (scale, batch, box). Round-2 pred loads are
// GATED on winning (losers fetch nothing -> no wasted DRAM traffic).
// Folds result directly into global fixed-point accumulators.
// ---------------------------------------------------------------------------
__device__ void winner_warp_body(int gwarp, int lane,
                                 float4 bb4, float4 hb4,
                                 int lab, int em, int ac, int hv,
                                 const float* __restrict__ p0,
                                 const float* __restrict__ p1,
                                 const float* __restrict__ p2) {
    const unsigned FULL = 0xffffffffu;
    const int s   = gwarp / (BB * NN);
    const int rem = gwarp % (BB * NN);
    const int b   = rem / NN;
    const int n   = rem % NN;

    const float* pred = (s == 0) ? p0 : ((s == 1) ? p1 : p2);
    const int   H  = (s == 0) ? 80 : ((s == 1) ? 40 : 20);
    const int   W  = H;
    const float sx = IMG / (float)W;
    const float sy = IMG / (float)H;

    // ---- per-lane box geometry (lane j = box j of this row) ----
    float mxv = fmaxf(fmaxf(bb4.x, bb4.y), fmaxf(bb4.z, bb4.w));
    float sc  = (mxv <= 1.5f) ? IMG : 1.f;       // _scale_box
    float x1 = bb4.x * sc, y1 = bb4.y * sc, x2 = bb4.z * sc, y2 = bb4.w * sc;
    float bw = x2 - x1, bh = y2 - y1;
    float cx = 0.5f * (x1 + x2), cy = 0.5f * (y1 + y2);
    int gx = (int)floorf(cx / sx);
    int gy = (int)floorf(cy / sy);
    int valid = (lane < NN) && (bw > 0.f) && (bh > 0.f) &&
                (gx >= 0) && (gy >= 0) && (gx < W) && (gy < H);
    float area = fmaxf(bb4.z - bb4.x, 0.f) * fmaxf(bb4.w - bb4.y, 0.f); // unscaled
    int gxc = min(max(gx, 0), W - 1);
    int gyc = min(max(gy, 0), H - 1);
    int cell = gyc * W + gxc;

    // ---- winner test for box n via ballot ----
    float area_n  = __shfl_sync(FULL, area, n);
    int   cell_n  = __shfl_sync(FULL, cell, n);
    int   valid_n = __shfl_sync(FULL, valid, n);
    bool beat = (lane < NN) && (lane != n) && valid && (cell == cell_n) &&
                (area < area_n || (area == area_n && lane < n));
    bool win = valid_n && (__ballot_sync(FULL, beat) == 0u);
    if (!win) return;

    // box-n geometry broadcast
    float x1n = __shfl_sync(FULL, x1, n);
    float y1n = __shfl_sync(FULL, y1, n);
    float bwn = __shfl_sync(FULL, bw, n);
    float bhn = __shfl_sync(FULL, bh, n);
    float cxn = __shfl_sync(FULL, cx, n);
    float cyn = __shfl_sync(FULL, cy, n);
    int   gxn = __shfl_sync(FULL, gx, n);
    int   gyn = __shfl_sync(FULL, gy, n);

    // head-n geometry
    float hmv = fmaxf(fmaxf(hb4.x, hb4.y), fmaxf(hb4.z, hb4.w));
    float hsc = (hmv <= 1.5f) ? IMG : 1.f;
    float hx1 = hb4.x * hsc, hy1 = hb4.y * hsc, hx2 = hb4.z * hsc, hy2 = hb4.w * hsc;
    float hx1n = __shfl_sync(FULL, hx1, n);
    float hy1n = __shfl_sync(FULL, hy1, n);
    float hx2n = __shfl_sync(FULL, hx2, n);
    float hy2n = __shfl_sync(FULL, hy2, n);
    bool hmask = (hv != 0) && (hx2n > hx1n) && (hy2n > hy1n);

    // ---- round 2: pred channel loads (warp-wide, cached, winners only) ----
    const float* cp = pred + (((size_t)b * H + gyn) * W + gxn) * CC;
    float chd = (lane < 9) ? ldg_plain(cp + lane) : 0.f;
    float v[5];
    #pragma unroll
    for (int k = 0; k < 5; k++) {
        int j = lane + 32 * k;
        v[k] = (j < NBC + NEC + NAC) ? ldg_plain(cp + 9 + j) : 0.f;
    }

    // ---- three group log-sum-exps ----
    float mB = -1e30f, mE = -1e30f, mA = -1e30f;
    #pragma unroll
    for (int k = 0; k < 5; k++) {
        int j = lane + 32 * k;
        if (j < NBC)                  mB = fmaxf(mB, v[k]);
        else if (j < NBC + NEC)       mE = fmaxf(mE, v[k]);
        else if (j < NBC + NEC + NAC) mA = fmaxf(mA, v[k]);
    }
    mB = wredmax(mB); mE = wredmax(mE); mA = wredmax(mA);
    float eB = 0.f, eE = 0.f, eA = 0.f;
    #pragma unroll
    for (int k = 0; k < 5; k++) {
        int j = lane + 32 * k;
        if (j < NBC)                  eB += expf(v[k] - mB);
        else if (j < NBC + NEC)       eE += expf(v[k] - mE);
        else if (j < NBC + NEC + NAC) eA += expf(v[k] - mA);
    }
    eB = wredf(eB); eE = wredf(eE); eA = wredf(eA);

    // ---- per-lane box/head/obj contributions ----
    float contrib = 0.f;
    if (lane == 0)      contrib = -L_OBJ * chd;
    else if (lane == 1) contrib = L_BOX * sl1(sigm(chd), cxn / sx - (float)gxn);
    else if (lane == 2) contrib = L_BOX * sl1(sigm(chd), cyn / sy - (float)gyn);
    else if (lane == 3) contrib = L_BOX * sl1(chd, logf(bwn / sx + 1e-6f));
    else if (lane == 4) contrib = L_BOX * sl1(chd, logf(bhn / sy + 1e-6f));
    else if (lane < 9 && hmask) {
        float ibw = 1.f / bwn, ibh = 1.f / bhn;
        float q = (lane == 5) ? (hx1n - x1n) * ibw
                : (lane == 6) ? (hy1n - y1n) * ibh
                : (lane == 7) ? (hx2n - x1n) * ibw
                :               (hy2n - y1n) * ibh;
        q = fminf(fmaxf(q, 0.f), 1.f);
        contrib = L_HEAD * sl1(sigm(chd), q);
    }
    contrib = wredf(contrib);

    // ---- CE terms (uniform broadcast loads; lines already resident) ----
    float ce = 0.f;
    if (lab != IGN_V) {
        int t = min(max(lab, 0), NBC - 1);
        ce += -(ldg_plain(cp + 9 + t) - mB - logf(eB));
    }
    if (em != IGN_V) {
        int t = min(max(em, 0), NEC - 1);
        ce += -(ldg_plain(cp + 9 + NBC + t) - mE - logf(eE));
    }
    if (ac != IGN_V) {
        int t = min(max(ac, 0), NAC - 1);
        ce += -(ldg_plain(cp + 9 + NBC + NEC + t) - mA - logf(eA));
    }

    if (lane == 0) {
        float wl = contrib + L_ATTR * ce;
        long long q = __double2ll_rn((double)wl * ACC_SCALE);
        atomicAdd(&g_num, (unsigned long long)q);
        atomicAdd(&g_pos, 1);
    }
}

// ---------------------------------------------------------------------------
// Fused kernel, 296 blocks x 512 threads (2 CTA/SM, one wave).
// DRAM-balanced: winner blocks [0,72) carry 360 obj cells + 16 winner warps
// (~58KB each), pure-obj blocks [72,296) carry 485 obj cells (~62KB each).
// Integer fixed-point atomics -> bit-deterministic. Last block finalizes.
// ---------------------------------------------------------------------------
__global__ void __launch_bounds__(512)
fused_loss_kernel(const float* __restrict__ p0,
                  const float* __restrict__ p1,
                  const float* __restrict__ p2,
                  const float* __restrict__ body,
                  const float* __restrict__ headb,
                  const int*   __restrict__ labels,
                  const int*   __restrict__ emotions,
                  const int*   __restrict__ actions,
                  const int*   __restrict__ head_valid,
                  float* __restrict__ out) {
    const int tid  = threadIdx.x;
    const int warp = tid >> 5;
    const int lane = tid & 31;
    const bool is_win_blk = (blockIdx.x < NWINB);

    // ---- winner round-1 loads issued FIRST (independent; overlap drain) ----
    float4 bb4 = make_float4(0.f, 0.f, 0.f, 0.f);
    float4 hb4 = make_float4(0.f, 0.f, 0.f, 0.f);
    int lab = IGN_V, em = IGN_V, ac = IGN_V, hv = 0, gwarp = 0;
    if (is_win_blk) {
        gwarp = blockIdx.x * 16 + warp;
        const int rem = gwarp % (BB * NN);
        const int b   = rem / NN;
        const int n   = rem % NN;
        if (lane < NN) {
            bb4 = __ldg((const float4*)(body  + ((size_t)b * NN + lane) * 4));
            hb4 = __ldg((const float4*)(headb + ((size_t)b * NN + lane) * 4));
        }
        lab = __ldg(labels     + b * NN + n);
        em  = __ldg(emotions   + b * NN + n);
        ac  = __ldg(actions    + b * NN + n);
        hv  = __ldg(head_valid + b * NN + n);
    }

    // ---- obj slice: DRAM-balanced split ----
    int i, ncells;
    if (is_win_blk) { i = blockIdx.x * WIN_CELLS + tid;                 ncells = WIN_CELLS; }
    else            { i = OBJ_BASE + (blockIdx.x - NWINB) * OBJ_CELLS + tid; ncells = OBJ_CELLS; }
    float xo = -1e30f;
    const bool live = (tid < ncells) && (i < TOT_CELLS);
    if (live) {
        const float* p; int loc;
        if (i < T0_CELLS)                  { p = p0; loc = i; }
        else if (i < T0_CELLS + T1_CELLS)  { p = p1; loc = i - T0_CELLS; }
        else                               { p = p2; loc = i - T0_CELLS - T1_CELLS; }
        xo = ldg_plain(p + (size_t)loc * CC);
    }

    // ---- winner logic (round-2 gathers land inside the obj drain) ----
    if (is_win_blk) {
        winner_warp_body(gwarp, lane, bb4, hb4, lab, em, ac, hv, p0, p1, p2);
    }

    // ---- obj softplus + block reduction ----
    float acc = live ? softplusf(xo) : 0.f;
    acc = wredf(acc);
    __shared__ float sh[16];
    if (lane == 0) sh[warp] = acc;
    __syncthreads();

    // ---- fold partials + completion protocol ----
    __shared__ bool s_last;
    if (tid == 0) {
        float blockL = 0.f;
        #pragma unroll
        for (int w = 0; w < 16; w++) blockL += sh[w];
        blockL *= L_OBJ;
        long long q = __double2ll_rn((double)blockL * ACC_SCALE);
        atomicAdd(&g_num, (unsigned long long)q);
        __threadfence();
        unsigned int old = atomicAdd(&g_done, 1u);
        s_last = (old == (unsigned int)(NBLKS - 1));
    }
    __syncthreads();
    if (!s_last) return;

    if (tid == 0) {
        long long num = (long long)g_num;
        int pos = g_pos;
        out[0] = (float)((double)num / ACC_SCALE / (double)max(pos, 1));
        // reset for next graph replay
        g_num  = 0ull;
        g_pos  = 0;
        g_done = 0u;
    }
}

// ---------------------------------------------------------------------------
extern "C" void kernel_launch(void* const* d_in, const int* in_sizes, int n_in,
                              void* d_out, int out_size) {
    const float* p0       = (const float*)d_in[0];
    const float* p1       = (const float*)d_in[1];
    const float* p2       = (const float*)d_in[2];
    const float* body     = (const float*)d_in[3];
    const float* headb    = (const float*)d_in[4];
    const int*   labels   = (const int*)d_in[5];
    const int*   emotions = (const int*)d_in[6];
    const int*   actions  = (const int*)d_in[7];
    const int*   head_valid = (const int*)d_in[8];
    float* out = (float*)d_out;

    fused_loss_kernel<<<NBLKS, 512>>>(p0, p1, p2, body, headb,
                                      labels, emotions, actions, head_valid, out);
}

// round 14
// speedup vs baseline: 1.0269x; 1.0269x over previous
#include <cuda_runtime.h>
#include <math.h>

// ---------------- problem constants ----------------
#define BB   16     // batch
#define NN   24     // boxes per image
#define CC   149    // 1 obj + 2 xy + 2 wh + 4 head + 120 + 8 + 12
#define NBC  120
#define NEC  8
#define NAC  12
#define IGN_V (-100)
#define IMG  640.0f

#define L_OBJ  1.0f
#define L_BOX  5.0f
#define L_HEAD 2.0f
#define L_ATTR 1.0f

#define T0_CELLS (BB * 80 * 80)   // 102400
#define T1_CELLS (BB * 40 * 40)   // 25600
#define T2_CELLS (BB * 20 * 20)   // 6400
#define TOT_CELLS (T0_CELLS + T1_CELLS + T2_CELLS)  // 134400

#define NWINB  72                  // blocks that ALSO run winner warps (72*16 = 1152)
#define NBLKS  296                 // total blocks = 2 * 148 SMs, one wave
#define CELLS_PER_BLK 455          // ceil(134400/296); uniform slices = best measured

// Fixed-point scale for the deterministic integer accumulators.
#define ACC_SCALE 1048576.0        // 2^20

// scratch (device globals). All self-reset -> graph-replay safe.
__device__ unsigned long long g_num  = 0;  // fixed-point loss numerator
__device__ int                g_pos  = 0;  // winner count
__device__ unsigned int       g_done = 0;  // completion counter

__device__ __forceinline__ float ldg_plain(const float* p) {
    float v;
    asm("ld.global.f32 %0, [%1];" : "=f"(v) : "l"(p));
    return v;
}

__device__ __forceinline__ float softplusf(float x) {
    return fmaxf(x, 0.f) + log1pf(expf(-fabsf(x)));
}
__device__ __forceinline__ float sigm(float x) { return 1.f / (1.f + expf(-x)); }
__device__ __forceinline__ float sl1(float p, float t) {
    float d = fabsf(p - t);
    return d < 1.f ? 0.5f * d * d : d - 0.5f;
}
__device__ __forceinline__ float wredf(float v) {
    #pragma unroll
    for (int o = 16; o > 0; o >>= 1) v += __shfl_xor_sync(0xffffffffu, v, o);
    return v;
}
__device__ __forceinline__ float wredmax(float v) {
    #pragma unroll
    for (int o = 16; o > 0; o >>= 1) v = fmaxf(v, __shfl_xor_sync(0xffffffffu, v, o));
    return v;
}

// ---------------------------------------------------------------------------
// Winner role: ONE WARP per (scale, batch, box). Round-1 data passed in
// (issued at block start, overlapped with obj loads). Round-2 pred loads are
// GATED on winning (losers fetch nothing). Folds result directly into the
// global fixed-point accumulators (integer atomics = bit-deterministic).
// ---------------------------------------------------------------------------
__device__ void winner_warp_body(int gwarp, int lane,
                                 float4 bb4, float4 hb4,
                                 int lab, int em, int ac, int hv,
                                 const float* __restrict__ p0,
                                 const float* __restrict__ p1,
                                 const float* __restrict__ p2) {
    const unsigned FULL = 0xffffffffu;
    const int s   = gwarp / (BB * NN);
    const int rem = gwarp % (BB * NN);
    const int b   = rem / NN;
    const int n   = rem % NN;

    const float* pred = (s == 0) ? p0 : ((s == 1) ? p1 : p2);
    const int   H  = (s == 0) ? 80 : ((s == 1) ? 40 : 20);
    const int   W  = H;
    const float sx = IMG / (float)W;
    const float sy = IMG / (float)H;

    // ---- per-lane box geometry (lane j = box j of this row) ----
    float mxv = fmaxf(fmaxf(bb4.x, bb4.y), fmaxf(bb4.z, bb4.w));
    float sc  = (mxv <= 1.5f) ? IMG : 1.f;       // _scale_box
    float x1 = bb4.x * sc, y1 = bb4.y * sc, x2 = bb4.z * sc, y2 = bb4.w * sc;
    float bw = x2 - x1, bh = y2 - y1;
    float cx = 0.5f * (x1 + x2), cy = 0.5f * (y1 + y2);
    int gx = (int)floorf(cx / sx);
    int gy = (int)floorf(cy / sy);
    int valid = (lane < NN) && (bw > 0.f) && (bh > 0.f) &&
                (gx >= 0) && (gy >= 0) && (gx < W) && (gy < H);
    float area = fmaxf(bb4.z - bb4.x, 0.f) * fmaxf(bb4.w - bb4.y, 0.f); // unscaled
    int gxc = min(max(gx, 0), W - 1);
    int gyc = min(max(gy, 0), H - 1);
    int cell = gyc * W + gxc;

    // ---- winner test for box n via ballot ----
    float area_n  = __shfl_sync(FULL, area, n);
    int   cell_n  = __shfl_sync(FULL, cell, n);
    int   valid_n = __shfl_sync(FULL, valid, n);
    bool beat = (lane < NN) && (lane != n) && valid && (cell == cell_n) &&
                (area < area_n || (area == area_n && lane < n));
    bool win = valid_n && (__ballot_sync(FULL, beat) == 0u);
    if (!win) return;

    // box-n geometry broadcast
    float x1n = __shfl_sync(FULL, x1, n);
    float y1n = __shfl_sync(FULL, y1, n);
    float bwn = __shfl_sync(FULL, bw, n);
    float bhn = __shfl_sync(FULL, bh, n);
    float cxn = __shfl_sync(FULL, cx, n);
    float cyn = __shfl_sync(FULL, cy, n);
    int   gxn = __shfl_sync(FULL, gx, n);
    int   gyn = __shfl_sync(FULL, gy, n);

    // head-n geometry
    float hmv = fmaxf(fmaxf(hb4.x, hb4.y), fmaxf(hb4.z, hb4.w));
    float hsc = (hmv <= 1.5f) ? IMG : 1.f;
    float hx1 = hb4.x * hsc, hy1 = hb4.y * hsc, hx2 = hb4.z * hsc, hy2 = hb4.w * hsc;
    float hx1n = __shfl_sync(FULL, hx1, n);
    float hy1n = __shfl_sync(FULL, hy1, n);
    float hx2n = __shfl_sync(FULL, hx2, n);
    float hy2n = __shfl_sync(FULL, hy2, n);
    bool hmask = (hv != 0) && (hx2n > hx1n) && (hy2n > hy1n);

    // ---- round 2: pred channel loads (warp-wide, cached, winners only) ----
    const float* cp = pred + (((size_t)b * H + gyn) * W + gxn) * CC;
    float chd = (lane < 9) ? ldg_plain(cp + lane) : 0.f;
    float v[5];
    #pragma unroll
    for (int k = 0; k < 5; k++) {
        int j = lane + 32 * k;
        v[k] = (j < NBC + NEC + NAC) ? ldg_plain(cp + 9 + j) : 0.f;
    }

    // ---- three group log-sum-exps ----
    float mB = -1e30f, mE = -1e30f, mA = -1e30f;
    #pragma unroll
    for (int k = 0; k < 5; k++) {
        int j = lane + 32 * k;
        if (j < NBC)                  mB = fmaxf(mB, v[k]);
        else if (j < NBC + NEC)       mE = fmaxf(mE, v[k]);
        else if (j < NBC + NEC + NAC) mA = fmaxf(mA, v[k]);
    }
    mB = wredmax(mB); mE = wredmax(mE); mA = wredmax(mA);
    float eB = 0.f, eE = 0.f, eA = 0.f;
    #pragma unroll
    for (int k = 0; k < 5; k++) {
        int j = lane + 32 * k;
        if (j < NBC)                  eB += expf(v[k] - mB);
        else if (j < NBC + NEC)       eE += expf(v[k] - mE);
        else if (j < NBC + NEC + NAC) eA += expf(v[k] - mA);
    }
    eB = wredf(eB); eE = wredf(eE); eA = wredf(eA);

    // ---- per-lane box/head/obj contributions ----
    float contrib = 0.f;
    if (lane == 0)      contrib = -L_OBJ * chd;
    else if (lane == 1) contrib = L_BOX * sl1(sigm(chd), cxn / sx - (float)gxn);
    else if (lane == 2) contrib = L_BOX * sl1(sigm(chd), cyn / sy - (float)gyn);
    else if (lane == 3) contrib = L_BOX * sl1(chd, logf(bwn / sx + 1e-6f));
    else if (lane == 4) contrib = L_BOX * sl1(chd, logf(bhn / sy + 1e-6f));
    else if (lane < 9 && hmask) {
        float ibw = 1.f / bwn, ibh = 1.f / bhn;
        float q = (lane == 5) ? (hx1n - x1n) * ibw
                : (lane == 6) ? (hy1n - y1n) * ibh
                : (lane == 7) ? (hx2n - x1n) * ibw
                :               (hy2n - y1n) * ibh;
        q = fminf(fmaxf(q, 0.f), 1.f);
        contrib = L_HEAD * sl1(sigm(chd), q);
    }
    contrib = wredf(contrib);

    // ---- CE terms (uniform broadcast loads; lines already resident) ----
    float ce = 0.f;
    if (lab != IGN_V) {
        int t = min(max(lab, 0), NBC - 1);
        ce += -(ldg_plain(cp + 9 + t) - mB - logf(eB));
    }
    if (em != IGN_V) {
        int t = min(max(em, 0), NEC - 1);
        ce += -(ldg_plain(cp + 9 + NBC + t) - mE - logf(eE));
    }
    if (ac != IGN_V) {
        int t = min(max(ac, 0), NAC - 1);
        ce += -(ldg_plain(cp + 9 + NBC + NEC + t) - mA - logf(eA));
    }

    if (lane == 0) {
        float wl = contrib + L_ATTR * ce;
        long long q = __double2ll_rn((double)wl * ACC_SCALE);
        atomicAdd(&g_num, (unsigned long long)q);
        atomicAdd(&g_pos, 1);
    }
}

// ---------------------------------------------------------------------------
// Fused kernel, 296 blocks x 512 threads (one clean 2-CTA/SM wave):
//   EVERY block: equal 455-cell slice of the obj softplus sum (1 load/thread)
//   blocks [0,72): additionally 16 winner warps each (round-1 loads issued
//                  FIRST so the dependent chain overlaps the obj drain)
// Integer fixed-point atomics -> bit-deterministic. Last block finalizes.
// ---------------------------------------------------------------------------
__global__ void __launch_bounds__(512)
fused_loss_kernel(const float* __restrict__ p0,
                  const float* __restrict__ p1,
                  const float* __restrict__ p2,
                  const float* __restrict__ body,
                  const float* __restrict__ headb,
                  const int*   __restrict__ labels,
                  const int*   __restrict__ emotions,
                  const int*   __restrict__ actions,
                  const int*   __restrict__ head_valid,
                  float* __restrict__ out) {
    const int tid  = threadIdx.x;
    const int warp = tid >> 5;
    const int lane = tid & 31;
    const bool is_win_blk = (blockIdx.x < NWINB);

    // ---- winner round-1 loads issued FIRST (independent; overlap drain) ----
    float4 bb4 = make_float4(0.f, 0.f, 0.f, 0.f);
    float4 hb4 = make_float4(0.f, 0.f, 0.f, 0.f);
    int lab = IGN_V, em = IGN_V, ac = IGN_V, hv = 0, gwarp = 0;
    if (is_win_blk) {
        gwarp = blockIdx.x * 16 + warp;
        const int rem = gwarp % (BB * NN);
        const int b   = rem / NN;
        const int n   = rem % NN;
        if (lane < NN) {
            bb4 = __ldg((const float4*)(body  + ((size_t)b * NN + lane) * 4));
            hb4 = __ldg((const float4*)(headb + ((size_t)b * NN + lane) * 4));
        }
        lab = __ldg(labels     + b * NN + n);
        em  = __ldg(emotions   + b * NN + n);
        ac  = __ldg(actions    + b * NN + n);
        hv  = __ldg(head_valid + b * NN + n);
    }

    // ---- obj slice: every block carries an equal 455-cell slice ----
    const int i = blockIdx.x * CELLS_PER_BLK + tid;
    float xo = -1e30f;
    const bool live = (tid < CELLS_PER_BLK) && (i < TOT_CELLS);
    if (live) {
        const float* p; int loc;
        if (i < T0_CELLS)                  { p = p0; loc = i; }
        else if (i < T0_CELLS + T1_CELLS)  { p = p1; loc = i - T0_CELLS; }
        else                               { p = p2; loc = i - T0_CELLS - T1_CELLS; }
        xo = ldg_plain(p + (size_t)loc * CC);
    }

    // ---- winner logic (round-2 gathers land inside the obj drain) ----
    if (is_win_blk) {
        winner_warp_body(gwarp, lane, bb4, hb4, lab, em, ac, hv, p0, p1, p2);
    }

    // ---- obj softplus + block reduction ----
    float acc = live ? softplusf(xo) : 0.f;
    acc = wredf(acc);
    __shared__ float sh[16];
    if (lane == 0) sh[warp] = acc;
    __syncthreads();

    // ---- fold partials + completion protocol ----
    __shared__ bool s_last;
    if (tid == 0) {
        float blockL = 0.f;
        #pragma unroll
        for (int w = 0; w < 16; w++) blockL += sh[w];
        blockL *= L_OBJ;
        long long q = __double2ll_rn((double)blockL * ACC_SCALE);
        atomicAdd(&g_num, (unsigned long long)q);
        __threadfence();
        unsigned int old = atomicAdd(&g_done, 1u);
        s_last = (old == (unsigned int)(NBLKS - 1));
    }
    __syncthreads();
    if (!s_last) return;

    if (tid == 0) {
        long long num = (long long)g_num;
        int pos = g_pos;
        out[0] = (float)((double)num / ACC_SCALE / (double)max(pos, 1));
        // reset for next graph replay
        g_num  = 0ull;
        g_pos  = 0;
        g_done = 0u;
    }
}

// ---------------------------------------------------------------------------
extern "C" void kernel_launch(void* const* d_in, const int* in_sizes, int n_in,
                              void* d_out, int out_size) {
    const float* p0       = (const float*)d_in[0];
    const float* p1       = (const float*)d_in[1];
    const float* p2       = (const float*)d_in[2];
    const float* body     = (const float*)d_in[3];
    const float* headb    = (const float*)d_in[4];
    const int*   labels   = (const int*)d_in[5];
    const int*   emotions = (const int*)d_in[6];
    const int*   actions  = (const int*)d_in[7];
    const int*   head_valid = (const int*)d_in[8];
    float* out = (float*)d_out;

    fused_loss_kernel<<<NBLKS, 512>>>(p0, p1, p2, body, headb,
                                      labels, emotions, actions, head_valid, out);
}